// round 2
// baseline (speedup 1.0000x reference)
#include <cuda_runtime.h>
#include <math.h>

#define BB 256
#define NCH 32
#define TT 2000
#define NTF 4
#define NSF 40
#define NSUB 20
#define TK 25
#define NCLS 4
#define NPAIR 210        // NSUB*(NSUB+1)/2
#define NCHUNK 8
#define TC 250           // 8*250 = 2000
#define XS_STRIDE 275    // TC + 24 halo, padded
#define YS_STRIDE 257    // TC padded to odd stride (bank decorrelation)
#define NSWEEP 12

// Scratch (no allocations allowed): projected weights + per-chunk partial sums.
__device__ float g_Wc[128 * 20];               // [(g*32+c)*20 + s]
__device__ float g_part[NCHUNK][BB][232];      // [chunk][b][0..209]=sum y_i y_j, [210..229]=sum y_i

// ---------------------------------------------------------------------------
// Precompute Wc[s,g,c] = sum_f W_bimap[s,f] * conv2_w[f,g,c]
// (conv/cls biases other than clf_b provably cancel in the covariance)
// ---------------------------------------------------------------------------
__global__ void prep_kernel(const float* __restrict__ conv2_w,
                            const float* __restrict__ W_bimap) {
    int idx = blockIdx.x * blockDim.x + threadIdx.x;
    if (idx < 128 * 20) {
        int s = idx % 20, gc = idx / 20;   // gc = g*32 + c
        float acc = 0.f;
        #pragma unroll 8
        for (int f = 0; f < NSF; ++f)
            acc += W_bimap[s * NSF + f] * conv2_w[f * 128 + gc];
        g_Wc[gc * 20 + s] = acc;
    }
}

// ---------------------------------------------------------------------------
// Fused: reflect-pad temporal conv (4 kernels) -> 20-dim projection -> partial
// covariance sums per (chunk, batch). One block per (chunk, batch).
// ---------------------------------------------------------------------------
__global__ void conv_cov_kernel(const float* __restrict__ x,
                                const float* __restrict__ w1) {
    extern __shared__ float smem[];
    float* xs  = smem;                      // 32 * XS_STRIDE
    float* ys  = xs + NCH * XS_STRIDE;      // 20 * YS_STRIDE
    float* wcs = ys + 20 * YS_STRIDE;       // 2560
    float* w1s = wcs + 2560;                // 100

    const int tid = threadIdx.x;
    const int chunk = blockIdx.x, b = blockIdx.y;
    const int t0 = chunk * TC;

    // Load x tile (with 12-left/12-right reflect padding at global edges)
    const float* xb = x + (size_t)b * NCH * TT;
    for (int idx = tid; idx < NCH * (TC + 24); idx += blockDim.x) {
        int c = idx / (TC + 24), tt = idx % (TC + 24);
        int gi = t0 + tt - 12;
        if (gi < 0) gi = -gi;
        if (gi >= TT) gi = 2 * TT - 2 - gi;
        xs[c * XS_STRIDE + tt] = xb[c * TT + gi];
    }
    for (int idx = tid; idx < 2560; idx += blockDim.x) wcs[idx] = g_Wc[idx];
    for (int idx = tid; idx < NTF * TK; idx += blockDim.x) w1s[idx] = w1[idx];
    __syncthreads();

    // Each active thread computes y[:,t] for two consecutive t
    if (tid < TC / 2) {
        const int tl = 2 * tid;
        float y0[20], y1[20];
        #pragma unroll
        for (int s = 0; s < 20; ++s) { y0[s] = 0.f; y1[s] = 0.f; }

        for (int c = 0; c < NCH; ++c) {
            float win[26];
            const float* xr = &xs[c * XS_STRIDE + tl];
            #pragma unroll
            for (int j = 0; j < 26; ++j) win[j] = xr[j];

            #pragma unroll
            for (int g = 0; g < NTF; ++g) {
                float a = 0.f, e = 0.f;
                #pragma unroll
                for (int k = 0; k < TK; ++k) {
                    float w = w1s[g * TK + k];
                    a += w * win[k];
                    e += w * win[k + 1];
                }
                const float4* wc4 = (const float4*)&wcs[(g * 32 + c) * 20];
                #pragma unroll
                for (int q = 0; q < 5; ++q) {
                    float4 wv = wc4[q];
                    y0[4*q+0] += wv.x * a; y0[4*q+1] += wv.y * a;
                    y0[4*q+2] += wv.z * a; y0[4*q+3] += wv.w * a;
                    y1[4*q+0] += wv.x * e; y1[4*q+1] += wv.y * e;
                    y1[4*q+2] += wv.z * e; y1[4*q+3] += wv.w * e;
                }
            }
        }
        #pragma unroll
        for (int s = 0; s < 20; ++s) {
            ys[s * YS_STRIDE + tl]     = y0[s];
            ys[s * YS_STRIDE + tl + 1] = y1[s];
        }
    }
    __syncthreads();

    // Partial second-moment sums (210 pairs) + first-moment sums (20)
    for (int p = tid; p < 230; p += blockDim.x) {
        float acc = 0.f;
        if (p < NPAIR) {
            int i = 0, rem = p;
            while (rem >= 20 - i) { rem -= 20 - i; ++i; }
            int j = i + rem;
            const float* ri = &ys[i * YS_STRIDE];
            const float* rj = &ys[j * YS_STRIDE];
            for (int t = 0; t < TC; ++t) acc += ri[t] * rj[t];
        } else {
            const float* ri = &ys[(p - NPAIR) * YS_STRIDE];
            for (int t = 0; t < TC; ++t) acc += ri[t];
        }
        g_part[chunk][b][p] = acc;
    }
}

// ---------------------------------------------------------------------------
// Per-batch: assemble S (20x20), parallel-order Jacobi eig (warp-cooperative),
// matrix log with eigenvalue clamp, triu-vectorize, classifier.
// ---------------------------------------------------------------------------
__global__ void eig_kernel(const float* __restrict__ clf_w,
                           const float* __restrict__ clf_b,
                           float* __restrict__ out) {
    __shared__ float S[20][21];
    __shared__ float U[20][21];
    __shared__ float m[20], lw[20];
    __shared__ float cs[10], sn[10];
    __shared__ int   pa[10], qa[10];

    const int lane = threadIdx.x;
    const int b = blockIdx.x;

    if (lane < 20) {
        float acc = 0.f;
        #pragma unroll
        for (int ch = 0; ch < NCHUNK; ++ch) acc += g_part[ch][b][NPAIR + lane];
        m[lane] = acc;
    }
    __syncwarp();

    for (int p = lane; p < NPAIR; p += 32) {
        float acc = 0.f;
        #pragma unroll
        for (int ch = 0; ch < NCHUNK; ++ch) acc += g_part[ch][b][p];
        int i = 0, rem = p;
        while (rem >= 20 - i) { rem -= 20 - i; ++i; }
        int j = i + rem;
        float v = (acc - m[i] * m[j] * (1.0f / TT)) * (1.0f / (TT - 1));
        S[i][j] = v; S[j][i] = v;
    }
    for (int idx = lane; idx < 400; idx += 32) {
        int i = idx / 20, j = idx % 20;
        U[i][j] = (i == j) ? 1.f : 0.f;
    }
    __syncwarp();

    // Parallel-order (circle method) two-sided Jacobi: 10 disjoint rotations/step
    for (int sweep = 0; sweep < NSWEEP; ++sweep) {
        for (int r = 0; r < 19; ++r) {
            if (lane < 10) {
                int posa = lane, posb = 19 - lane;
                int p = (posa == 0) ? 0 : 1 + ((posa - 1 + r) % 19);
                int q = 1 + ((posb - 1 + r) % 19);
                float app = S[p][p], aqq = S[q][q], apq = S[p][q];
                float c = 1.f, s = 0.f;
                if (fabsf(apq) > 1e-12f) {
                    float tau = (aqq - app) / (2.f * apq);
                    float t = copysignf(1.f / (fabsf(tau) + sqrtf(1.f + tau * tau)), tau);
                    c = rsqrtf(1.f + t * t);
                    s = t * c;
                }
                cs[lane] = c; sn[lane] = s; pa[lane] = p; qa[lane] = q;
            }
            __syncwarp();
            // A <- A * J   (disjoint column pairs)
            for (int idx = lane; idx < 200; idx += 32) {
                int pr = idx / 20, k = idx % 20;
                int p = pa[pr], q = qa[pr];
                float c = cs[pr], s = sn[pr];
                float akp = S[k][p], akq = S[k][q];
                S[k][p] = c * akp - s * akq;
                S[k][q] = s * akp + c * akq;
            }
            __syncwarp();
            // A <- J^T * A  (disjoint row pairs)
            for (int idx = lane; idx < 200; idx += 32) {
                int pr = idx / 20, k = idx % 20;
                int p = pa[pr], q = qa[pr];
                float c = cs[pr], s = sn[pr];
                float apk = S[p][k], aqk = S[q][k];
                S[p][k] = c * apk - s * aqk;
                S[q][k] = s * apk + c * aqk;
            }
            __syncwarp();
            // U <- U * J
            for (int idx = lane; idx < 200; idx += 32) {
                int pr = idx / 20, k = idx % 20;
                int p = pa[pr], q = qa[pr];
                float c = cs[pr], s = sn[pr];
                float ukp = U[k][p], ukq = U[k][q];
                U[k][p] = c * ukp - s * ukq;
                U[k][q] = s * ukp + c * ukq;
            }
            __syncwarp();
        }
    }

    if (lane < 20) lw[lane] = logf(fmaxf(S[lane][lane], 1e-4f));
    __syncwarp();

    // z = triu(L) * scale;  out = z @ clf_w^T + clf_b
    float o0 = 0.f, o1 = 0.f, o2 = 0.f, o3 = 0.f;
    const float SQ2 = 1.41421356237309515f;
    for (int p = lane; p < NPAIR; p += 32) {
        int i = 0, rem = p;
        while (rem >= 20 - i) { rem -= 20 - i; ++i; }
        int j = i + rem;
        float L = 0.f;
        #pragma unroll
        for (int mm = 0; mm < 20; ++mm) L += U[i][mm] * lw[mm] * U[j][mm];
        float z = L * ((i == j) ? 1.f : SQ2);
        o0 += z * clf_w[0 * NPAIR + p];
        o1 += z * clf_w[1 * NPAIR + p];
        o2 += z * clf_w[2 * NPAIR + p];
        o3 += z * clf_w[3 * NPAIR + p];
    }
    #pragma unroll
    for (int off = 16; off; off >>= 1) {
        o0 += __shfl_down_sync(0xffffffffu, o0, off);
        o1 += __shfl_down_sync(0xffffffffu, o1, off);
        o2 += __shfl_down_sync(0xffffffffu, o2, off);
        o3 += __shfl_down_sync(0xffffffffu, o3, off);
    }
    if (lane == 0) {
        out[b * 4 + 0] = o0 + clf_b[0];
        out[b * 4 + 1] = o1 + clf_b[1];
        out[b * 4 + 2] = o2 + clf_b[2];
        out[b * 4 + 3] = o3 + clf_b[3];
    }
}

// ---------------------------------------------------------------------------
extern "C" void kernel_launch(void* const* d_in, const int* in_sizes, int n_in,
                              void* d_out, int out_size) {
    const float* x       = (const float*)d_in[0];
    const float* conv1_w = (const float*)d_in[1];
    // d_in[2] = conv1_b : cancels in covariance
    const float* conv2_w = (const float*)d_in[3];
    // d_in[4] = conv2_b : cancels in covariance
    const float* W_bimap = (const float*)d_in[5];
    const float* clf_w   = (const float*)d_in[6];
    const float* clf_b   = (const float*)d_in[7];
    float* out = (float*)d_out;

    size_t smem_bytes = (size_t)(NCH * XS_STRIDE + 20 * YS_STRIDE + 2560 + 100) * sizeof(float);
    cudaFuncSetAttribute(conv_cov_kernel,
                         cudaFuncAttributeMaxDynamicSharedMemorySize,
                         (int)smem_bytes);

    prep_kernel<<<10, 256>>>(conv2_w, W_bimap);
    conv_cov_kernel<<<dim3(NCHUNK, BB), 128, smem_bytes>>>(x, conv1_w);
    eig_kernel<<<BB, 32>>>(clf_w, clf_b, out);
}

// round 3
// speedup vs baseline: 1.2804x; 1.2804x over previous
#include <cuda_runtime.h>
#include <math.h>

#define BB 256
#define NCH 32
#define TT 2000
#define NTF 4
#define NSF 40
#define NSUB 20
#define TK 25
#define NCLS 4
#define NPAIR 210        // NSUB*(NSUB+1)/2
#define NCHUNK 8
#define TC 250           // 8*250 = 2000
#define XS_STRIDE 276    // TC + 24 halo = 274, padded even (8B alignment for LDS.64)
#define YS_STRIDE 258    // TC padded, even (8B alignment)
#define NSWEEP 8

typedef unsigned long long ull;

// Scratch (no allocations allowed): projected weights + per-chunk partial sums.
__device__ float g_Wc[128 * 20];               // [(g*32+c)*20 + s]
__device__ float g_part[NCHUNK][BB][232];      // [chunk][b][0..209]=sum y_i y_j, [210..229]=sum y_i

// ---- packed fp32x2 helpers (FFMA2 path: 2x fp32 FMA throughput on sm_103a) ----
__device__ __forceinline__ void fma2(ull& d, ull a, ull b) {
    asm("fma.rn.f32x2 %0, %1, %2, %0;" : "+l"(d) : "l"(a), "l"(b));
}
__device__ __forceinline__ ull pack2(float lo, float hi) {
    ull r; asm("mov.b64 %0, {%1, %2};" : "=l"(r) : "f"(lo), "f"(hi)); return r;
}
__device__ __forceinline__ float2 unpack2(ull v) {
    float2 f; asm("mov.b64 {%0, %1}, %2;" : "=f"(f.x), "=f"(f.y) : "l"(v)); return f;
}

// ---------------------------------------------------------------------------
// Precompute Wc[s,g,c] = sum_f W_bimap[s,f] * conv2_w[f,g,c]
// (conv biases provably cancel in the covariance)
// ---------------------------------------------------------------------------
__global__ void prep_kernel(const float* __restrict__ conv2_w,
                            const float* __restrict__ W_bimap) {
    int idx = blockIdx.x * blockDim.x + threadIdx.x;
    if (idx < 128 * 20) {
        int s = idx % 20, gc = idx / 20;   // gc = g*32 + c
        float acc = 0.f;
        #pragma unroll 8
        for (int f = 0; f < NSF; ++f)
            acc += W_bimap[s * NSF + f] * conv2_w[f * 128 + gc];
        g_Wc[gc * 20 + s] = acc;
    }
}

// ---------------------------------------------------------------------------
// Fused: reflect-pad temporal conv (4 taps-sets) -> 20-dim projection ->
// partial covariance sums per (chunk, batch). One block per (chunk, batch).
// All inner arithmetic uses packed f32x2 FMA.
// ---------------------------------------------------------------------------
__global__ void __launch_bounds__(128)
conv_cov_kernel(const float* __restrict__ x, const float* __restrict__ w1) {
    extern __shared__ float smem[];
    float* xs  = smem;                      // 32 * 276 = 8832
    float* ys  = xs + NCH * XS_STRIDE;      // 20 * 258 = 5160
    float* wcs = ys + 20 * YS_STRIDE;       // 2560
    float* w2f = wcs + 2560;                // 208 floats = 104 packed weight pairs

    const int tid = threadIdx.x;
    const int chunk = blockIdx.x, b = blockIdx.y;
    const int t0 = chunk * TC;

    // Load x tile (12-left/12-right reflect padding at global edges)
    const float* xb = x + (size_t)b * NCH * TT;
    for (int idx = tid; idx < NCH * (TC + 24); idx += blockDim.x) {
        int c = idx / (TC + 24), tt = idx % (TC + 24);
        int gi = t0 + tt - 12;
        if (gi < 0) gi = -gi;
        if (gi >= TT) gi = 2 * TT - 2 - gi;
        xs[c * XS_STRIDE + tt] = xb[c * TT + gi];
    }
    for (int idx = tid; idx < 2560; idx += blockDim.x) wcs[idx] = g_Wc[idx];
    // Packed conv1 weight pairs, two phases:
    //  phase A (output t):   pair i = (w[2i], w[2i+1]), i=12 -> (w[24], 0)
    //  phase B (output t+1): pair i = (w[2i-1], w[2i]),  i=0  -> (0, w[0])
    if (tid < 104) {
        int phase = tid / 52;
        int rem = tid % 52; int g = rem / 13, i = rem % 13;
        float lo, hi;
        if (phase == 0) {
            lo = w1[g * TK + 2 * i];
            hi = (i < 12) ? w1[g * TK + 2 * i + 1] : 0.f;
        } else {
            lo = (i == 0) ? 0.f : w1[g * TK + 2 * i - 1];
            hi = w1[g * TK + 2 * i];
        }
        w2f[2 * tid]     = lo;
        w2f[2 * tid + 1] = hi;
    }
    __syncthreads();

    // Each active thread computes y[:,t] for two consecutive t (tl, tl+1)
    if (tid < TC / 2) {
        const int tl = 2 * tid;
        ull acc0[10], acc1[10];              // (y0[2q],y0[2q+1]) / (y1[..])
        #pragma unroll
        for (int q = 0; q < 10; ++q) { acc0[q] = 0ull; acc1[q] = 0ull; }

        const ull* w2A = (const ull*)w2f;        // [g*13 + i]
        const ull* w2B = (const ull*)w2f + 52;

        for (int c = 0; c < NCH; ++c) {
            const ull* xr2 = (const ull*)&xs[c * XS_STRIDE + tl];  // 8B aligned
            ull win2[13];
            #pragma unroll
            for (int i = 0; i < 13; ++i) win2[i] = xr2[i];

            #pragma unroll
            for (int g = 0; g < NTF; ++g) {
                ull aA = 0ull, aB = 0ull;
                #pragma unroll
                for (int i = 0; i < 13; ++i) {
                    fma2(aA, win2[i], w2A[g * 13 + i]);
                    fma2(aB, win2[i], w2B[g * 13 + i]);
                }
                float2 fa = unpack2(aA); float a = fa.x + fa.y;  // h1[g,c,tl]
                float2 fb = unpack2(aB); float e = fb.x + fb.y;  // h1[g,c,tl+1]
                ull ad = pack2(a, a), ed = pack2(e, e);
                const ull* wv2 = (const ull*)&wcs[(g * 32 + c) * 20];
                #pragma unroll
                for (int q = 0; q < 10; ++q) {
                    fma2(acc0[q], wv2[q], ad);
                    fma2(acc1[q], wv2[q], ed);
                }
            }
        }
        #pragma unroll
        for (int q = 0; q < 10; ++q) {
            float2 u0 = unpack2(acc0[q]);
            float2 u1 = unpack2(acc1[q]);
            ys[(2 * q)     * YS_STRIDE + tl]     = u0.x;
            ys[(2 * q)     * YS_STRIDE + tl + 1] = u1.x;
            ys[(2 * q + 1) * YS_STRIDE + tl]     = u0.y;
            ys[(2 * q + 1) * YS_STRIDE + tl + 1] = u1.y;
        }
    }
    __syncthreads();

    // Partial second-moment sums (210 pairs) + first-moment sums (20), packed over t
    const ull ones = pack2(1.f, 1.f);
    for (int p = tid; p < 230; p += blockDim.x) {
        ull acc = 0ull;
        if (p < NPAIR) {
            int i = 0, rem = p;
            while (rem >= 20 - i) { rem -= 20 - i; ++i; }
            int j = i + rem;
            const ull* ri = (const ull*)&ys[i * YS_STRIDE];
            const ull* rj = (const ull*)&ys[j * YS_STRIDE];
            for (int t2 = 0; t2 < TC / 2; ++t2) fma2(acc, ri[t2], rj[t2]);
        } else {
            const ull* ri = (const ull*)&ys[(p - NPAIR) * YS_STRIDE];
            for (int t2 = 0; t2 < TC / 2; ++t2) fma2(acc, ri[t2], ones);
        }
        float2 f = unpack2(acc);
        g_part[chunk][b][p] = f.x + f.y;
    }
}

// ---------------------------------------------------------------------------
// Per-batch: assemble S (20x20), parallel-order Jacobi eig (warp-cooperative),
// matrix log with eigenvalue clamp, triu-vectorize, classifier.
// ---------------------------------------------------------------------------
__global__ void eig_kernel(const float* __restrict__ clf_w,
                           const float* __restrict__ clf_b,
                           float* __restrict__ out) {
    __shared__ float S[20][21];
    __shared__ float U[20][21];
    __shared__ float m[20], lw[20];
    __shared__ float cs[10], sn[10];
    __shared__ int   pa[10], qa[10];

    const int lane = threadIdx.x;
    const int b = blockIdx.x;

    if (lane < 20) {
        float acc = 0.f;
        #pragma unroll
        for (int ch = 0; ch < NCHUNK; ++ch) acc += g_part[ch][b][NPAIR + lane];
        m[lane] = acc;
    }
    __syncwarp();

    for (int p = lane; p < NPAIR; p += 32) {
        float acc = 0.f;
        #pragma unroll
        for (int ch = 0; ch < NCHUNK; ++ch) acc += g_part[ch][b][p];
        int i = 0, rem = p;
        while (rem >= 20 - i) { rem -= 20 - i; ++i; }
        int j = i + rem;
        float v = (acc - m[i] * m[j] * (1.0f / TT)) * (1.0f / (TT - 1));
        S[i][j] = v; S[j][i] = v;
    }
    for (int idx = lane; idx < 400; idx += 32) {
        int i = idx / 20, j = idx % 20;
        U[i][j] = (i == j) ? 1.f : 0.f;
    }
    __syncwarp();

    // Parallel-order (circle method) two-sided Jacobi: 10 disjoint rotations/step.
    // U-update fused into the column pass (both are right-multiplies by J).
    for (int sweep = 0; sweep < NSWEEP; ++sweep) {
        for (int r = 0; r < 19; ++r) {
            if (lane < 10) {
                int p = (lane == 0) ? 0 : 1 + ((lane - 1 + r) % 19);
                int q = 1 + ((18 - lane + r) % 19);
                float app = S[p][p], aqq = S[q][q], apq = S[p][q];
                float c = 1.f, s = 0.f;
                if (fabsf(apq) > 1e-12f) {
                    float tau = __fdividef(aqq - app, 2.f * apq);
                    float t = copysignf(__fdividef(1.f, fabsf(tau) + __fsqrt_rn(1.f + tau * tau)), tau);
                    c = rsqrtf(1.f + t * t);
                    s = t * c;
                }
                cs[lane] = c; sn[lane] = s; pa[lane] = p; qa[lane] = q;
            }
            __syncwarp();
            // A <- A*J and U <- U*J (disjoint column pairs)
            #pragma unroll
            for (int it = 0; it < 7; ++it) {
                int idx = lane + it * 32;
                if (idx < 200) {
                    int pr = idx / 20, k = idx - pr * 20;
                    int p = pa[pr], q = qa[pr];
                    float c = cs[pr], s = sn[pr];
                    float akp = S[k][p], akq = S[k][q];
                    S[k][p] = c * akp - s * akq;
                    S[k][q] = s * akp + c * akq;
                    float ukp = U[k][p], ukq = U[k][q];
                    U[k][p] = c * ukp - s * ukq;
                    U[k][q] = s * ukp + c * ukq;
                }
            }
            __syncwarp();
            // A <- J^T*A (disjoint row pairs)
            #pragma unroll
            for (int it = 0; it < 7; ++it) {
                int idx = lane + it * 32;
                if (idx < 200) {
                    int pr = idx / 20, k = idx - pr * 20;
                    int p = pa[pr], q = qa[pr];
                    float c = cs[pr], s = sn[pr];
                    float apk = S[p][k], aqk = S[q][k];
                    S[p][k] = c * apk - s * aqk;
                    S[q][k] = s * apk + c * aqk;
                }
            }
            __syncwarp();
        }
    }

    if (lane < 20) lw[lane] = logf(fmaxf(S[lane][lane], 1e-4f));
    __syncwarp();

    // z = triu(L) * scale;  out = z @ clf_w^T + clf_b
    float o0 = 0.f, o1 = 0.f, o2 = 0.f, o3 = 0.f;
    const float SQ2 = 1.41421356237309515f;
    for (int p = lane; p < NPAIR; p += 32) {
        int i = 0, rem = p;
        while (rem >= 20 - i) { rem -= 20 - i; ++i; }
        int j = i + rem;
        float L = 0.f;
        #pragma unroll
        for (int mm = 0; mm < 20; ++mm) L += U[i][mm] * lw[mm] * U[j][mm];
        float z = L * ((i == j) ? 1.f : SQ2);
        o0 += z * clf_w[0 * NPAIR + p];
        o1 += z * clf_w[1 * NPAIR + p];
        o2 += z * clf_w[2 * NPAIR + p];
        o3 += z * clf_w[3 * NPAIR + p];
    }
    #pragma unroll
    for (int off = 16; off; off >>= 1) {
        o0 += __shfl_down_sync(0xffffffffu, o0, off);
        o1 += __shfl_down_sync(0xffffffffu, o1, off);
        o2 += __shfl_down_sync(0xffffffffu, o2, off);
        o3 += __shfl_down_sync(0xffffffffu, o3, off);
    }
    if (lane == 0) {
        out[b * 4 + 0] = o0 + clf_b[0];
        out[b * 4 + 1] = o1 + clf_b[1];
        out[b * 4 + 2] = o2 + clf_b[2];
        out[b * 4 + 3] = o3 + clf_b[3];
    }
}

// ---------------------------------------------------------------------------
extern "C" void kernel_launch(void* const* d_in, const int* in_sizes, int n_in,
                              void* d_out, int out_size) {
    const float* x       = (const float*)d_in[0];
    const float* conv1_w = (const float*)d_in[1];
    // d_in[2] = conv1_b : cancels in covariance
    const float* conv2_w = (const float*)d_in[3];
    // d_in[4] = conv2_b : cancels in covariance
    const float* W_bimap = (const float*)d_in[5];
    const float* clf_w   = (const float*)d_in[6];
    const float* clf_b   = (const float*)d_in[7];
    float* out = (float*)d_out;

    size_t smem_bytes = (size_t)(NCH * XS_STRIDE + 20 * YS_STRIDE + 2560 + 208) * sizeof(float);
    cudaFuncSetAttribute(conv_cov_kernel,
                         cudaFuncAttributeMaxDynamicSharedMemorySize,
                         (int)smem_bytes);

    prep_kernel<<<10, 256>>>(conv2_w, W_bimap);
    conv_cov_kernel<<<dim3(NCHUNK, BB), 128, smem_bytes>>>(x, conv1_w);
    eig_kernel<<<BB, 32>>>(clf_w, clf_b, out);
}